// round 5
// baseline (speedup 1.0000x reference)
#include <cuda_runtime.h>
#include <cuda_bf16.h>

#define FULL 0xffffffffu

namespace {
constexpr int NB   = 32;
constexpr int NP   = 32;
constexpr int DD   = 12;
constexpr int PP   = 32;
constexpr int LL   = 1024;
constexpr int LOUT = 32;
constexpr int CPL  = 4;            // cols per lane
constexpr int WBLK = 32 * CPL;     // 128 cols per warp
constexpr int NBLK = LL / WBLK;    // 8 warps per problem pair
constexpr float BIGV = 1e30f;
}

// One CTA (8 warps, 256 thr) per (b, n-pair): handles patterns n0 = p and
// n1 = p + 16 against the same x[b]. Warp w owns column block w (128 cols);
// the x chunk registers are shared by both problems. Diagonal wavefront over
// rows with one __syncthreads per step; only the last-column carry crosses
// warps (via smem, barrier-ordered — the R4 lock-free variant raced).
// Row math (w == 1 exactly, since RHO = 1.0):
//   cur[j] = S[j] + min_{k<=j}( m[k] - S[k-1] ),  m[j] = min(D[i-1,j-1], D[i-1,j])
// Two independent DP chains per warp interleave their shfl-latency chains.
__global__ void __launch_bounds__(256, 2)
dtw_fused_kernel(const float* __restrict__ x,
                 const float* __restrict__ patts,
                 float* __restrict__ out)
{
    const int gid  = blockIdx.x;        // 0..511
    const int b    = gid >> 4;
    const int np   = gid & 15;          // pair index; n = np and np+16
    const int w    = threadIdx.x >> 5;  // column block 0..7
    const int lane = threadIdx.x & 31;

    __shared__ float carry[2][NBLK - 1][PP];   // carry[p][w][i] = D_p[i][(w+1)*WBLK-1]

    // Pattern data for both problems; lane holds column `lane`; store -2*p.
    float prow[2][DD];
    float p2[2] = {0.0f, 0.0f};
    #pragma unroll
    for (int p = 0; p < 2; ++p) {
        const float* pp = patts + (np + 16 * p) * (DD * PP) + lane;
        #pragma unroll
        for (int d = 0; d < DD; ++d) {
            float v = pp[d * PP];
            p2[p] = fmaf(v, v, p2[p]);
            prow[p][d] = -2.0f * v;
        }
    }

    // x chunk for this warp's column block — shared by both problems.
    const float* xb = x + b * (DD * LL);
    const int j0 = w * WBLK;
    float xr[DD][CPL];
    float x2[CPL] = {0.f, 0.f, 0.f, 0.f};
    #pragma unroll
    for (int d = 0; d < DD; ++d) {
        float4 v = *reinterpret_cast<const float4*>(xb + d * LL + j0 + CPL * lane);
        xr[d][0] = v.x; xr[d][1] = v.y; xr[d][2] = v.z; xr[d][3] = v.w;
        #pragma unroll
        for (int k = 0; k < CPL; ++k) x2[k] = fmaf(xr[d][k], xr[d][k], x2[k]);
    }

    float Dp[2][CPL];                 // previous DP row per problem
    float bm[2] = {BIGV, BIGV};       // D[i-1][j0-1] per problem (prev step's bl)

    // Full row update for problem p, row i, left-carry bl. Returns cur in `cur`.
    auto rowcalc = [&](int p, int i, float bl, float cur[CPL]) {
        // cost row + local inclusive prefix + warp sum-scan
        float p2b = __shfl_sync(FULL, p2[p], i);
        float c[CPL];
        #pragma unroll
        for (int k = 0; k < CPL; ++k) c[k] = p2b + x2[k];
        #pragma unroll
        for (int d = 0; d < DD; ++d) {
            float pb = __shfl_sync(FULL, prow[p][d], i);
            #pragma unroll
            for (int k = 0; k < CPL; ++k) c[k] = fmaf(pb, xr[d][k], c[k]);
        }
        float s[CPL];
        s[0] = c[0];
        #pragma unroll
        for (int k = 1; k < CPL; ++k) s[k] = s[k - 1] + c[k];
        float tot = s[CPL - 1];
        #pragma unroll
        for (int o = 1; o < 32; o <<= 1) {
            float u = __shfl_up_sync(FULL, tot, o);
            if (lane >= o) tot += u;
        }
        const float eC = tot - s[CPL - 1];   // exclusive warp sum prefix

        // t[k] = min(up-left, up) - S[j-1]
        float tt[CPL];
        float shin = __shfl_up_sync(FULL, Dp[p][CPL - 1], 1);
        if (i == 0) {
            #pragma unroll
            for (int k = 0; k < CPL; ++k) tt[k] = BIGV;
        } else {
            float mprev = (lane == 0) ? bm[p] : shin;
            tt[0] = fminf(mprev, Dp[p][0]) - eC;
            #pragma unroll
            for (int k = 1; k < CPL; ++k)
                tt[k] = fminf(Dp[p][k - 1], Dp[p][k]) - (eC + s[k - 1]);
        }

        // prefix-min with left-entry bl injected at position -1
        float q[CPL];
        q[0] = (lane == 0) ? fminf(bl, tt[0]) : tt[0];
        #pragma unroll
        for (int k = 1; k < CPL; ++k) q[k] = fminf(q[k - 1], tt[k]);

        float mt = q[CPL - 1];
        #pragma unroll
        for (int o = 1; o < 32; o <<= 1)
            mt = fminf(mt, __shfl_up_sync(FULL, mt, o));   // OOR self-min: no-op
        float eprev = __shfl_up_sync(FULL, mt, 1);
        if (lane == 0) eprev = BIGV;

        #pragma unroll
        for (int k = 0; k < CPL; ++k)
            cur[k] = (eC + s[k]) + fminf(eprev, q[k]);

        #pragma unroll
        for (int k = 0; k < CPL; ++k) Dp[p][k] = cur[k];
    };

    #pragma unroll 1
    for (int t = 0; t < PP + NBLK - 1; ++t) {
        const int i = t - w;
        if (i >= 0 && i < PP) {
            // left-boundary carries (barrier-ordered smem from warp w-1)
            float bl0, bl1;
            if (w == 0) {
                bl0 = bl1 = (i == 0) ? 0.0f : BIGV;   // D[0,0] seed
            } else {
                bl0 = carry[0][w - 1][i];
                bl1 = carry[1][w - 1][i];
            }

            float cur0[CPL], cur1[CPL];
            rowcalc(0, i, bl0, cur0);
            rowcalc(1, i, bl1, cur1);

            if (w < NBLK - 1 && lane == 31) {
                carry[0][w][i] = cur0[CPL - 1];
                carry[1][w][i] = cur1[CPL - 1];
            }

            // output: cols 992..1023 live in last warp, lanes 24..31
            if (w == NBLK - 1 && lane >= 24) {
                const int off = i * LOUT + (lane - 24) * CPL;
                float* po0 = out + ((b * NP + np) * PP) * LOUT + off;
                float* po1 = out + ((b * NP + np + 16) * PP) * LOUT + off;
                *reinterpret_cast<float4*>(po0) = make_float4(cur0[0], cur0[1], cur0[2], cur0[3]);
                *reinterpret_cast<float4*>(po1) = make_float4(cur1[0], cur1[1], cur1[2], cur1[3]);
            }

            bm[0] = bl0;
            bm[1] = bl1;
        }
        __syncthreads();
    }
}

extern "C" void kernel_launch(void* const* d_in, const int* in_sizes, int n_in,
                              void* d_out, int out_size) {
    const float* x     = (const float*)d_in[0];   // [32, 12, 1024]
    const float* patts = (const float*)d_in[1];   // [32, 12, 32]
    float* out = (float*)d_out;                   // [32, 32, 32, 32]
    (void)in_sizes; (void)n_in; (void)out_size;
    dtw_fused_kernel<<<NB * (NP / 2), 256>>>(x, patts, out);
}

// round 6
// speedup vs baseline: 1.0343x; 1.0343x over previous
#include <cuda_runtime.h>
#include <cuda_bf16.h>

#define FULL 0xffffffffu

namespace {
constexpr int NB   = 32;
constexpr int NP   = 32;
constexpr int DD   = 12;
constexpr int PP   = 32;
constexpr int LL   = 1024;
constexpr int LOUT = 32;
constexpr int CPL  = 8;            // cols per lane
constexpr int WBLK = 32 * CPL;     // 256 cols per warp
constexpr int NBLK = LL / WBLK;    // 4 warps per (b,n)
constexpr float BIGV = 1e30f;
}

// One CTA (4 warps) per (b, n). Warp w owns column block w. Diagonal wavefront:
// at step t, warp w computes DP row i = t - w; one __syncthreads per step; the
// only cross-warp values are the last-column carries D[i][j0-1], D[i-1][j0-1]
// read from barrier-ordered smem (R4/R5's register bm was wrong at w=0,i=1).
// Row math (w == 1 exactly, RHO = 1.0):
//   cur[j] = S[j] + min_{k<=j}( m[k] - S[k-1] ),  m[j] = min(D[i-1,j-1], D[i-1,j])
// Software pipeline: cost+sum-scan of row i+1 (depends only on resident x/patt
// registers) is computed in the same step as the DP min-scan of row i, so the
// two shfl dependency chains interleave. A prep step at i == -1 fills sC/eC.
__global__ void __launch_bounds__(128, 3)
dtw_fused_kernel(const float* __restrict__ x,
                 const float* __restrict__ patts,
                 float* __restrict__ out)
{
    const int gid  = blockIdx.x;        // 0..1023
    const int b    = gid >> 5;
    const int n    = gid & 31;
    const int w    = threadIdx.x >> 5;  // column block 0..3
    const int lane = threadIdx.x & 31;

    __shared__ float carry[NBLK - 1][PP];   // carry[w][i] = D[i][(w+1)*WBLK - 1]

    // lane holds patts[n][d][lane]; store -2*p for the FMA form of sqdist.
    float prow[DD];
    float p2 = 0.0f;
    {
        const float* pp = patts + n * (DD * PP) + lane;
        #pragma unroll
        for (int d = 0; d < DD; ++d) {
            float v = pp[d * PP];
            p2 = fmaf(v, v, p2);
            prow[d] = -2.0f * v;
        }
    }

    // x chunk for this warp's column block, reused by all 32 rows.
    const float* xb = x + b * (DD * LL);
    const int j0 = w * WBLK;
    float xr[DD][CPL];
    float x2[CPL] = {0.f, 0.f, 0.f, 0.f, 0.f, 0.f, 0.f, 0.f};
    #pragma unroll
    for (int d = 0; d < DD; ++d) {
        const float* px = xb + d * LL + j0 + CPL * lane;
        float4 v0 = *reinterpret_cast<const float4*>(px);
        float4 v1 = *reinterpret_cast<const float4*>(px + 4);
        xr[d][0] = v0.x; xr[d][1] = v0.y; xr[d][2] = v0.z; xr[d][3] = v0.w;
        xr[d][4] = v1.x; xr[d][5] = v1.y; xr[d][6] = v1.z; xr[d][7] = v1.w;
        #pragma unroll
        for (int k = 0; k < CPL; ++k) x2[k] = fmaf(xr[d][k], xr[d][k], x2[k]);
    }

    float* outb = out + ((b * NP + n) * PP) * LOUT;

    // cost row i + local inclusive prefix + warp-exclusive sum
    auto costscan = [&](int i, float s[CPL], float& excl) {
        float p2b = __shfl_sync(FULL, p2, i);
        float c[CPL];
        #pragma unroll
        for (int k = 0; k < CPL; ++k) c[k] = p2b + x2[k];
        #pragma unroll
        for (int d = 0; d < DD; ++d) {
            float pb = __shfl_sync(FULL, prow[d], i);
            #pragma unroll
            for (int k = 0; k < CPL; ++k) c[k] = fmaf(pb, xr[d][k], c[k]);
        }
        s[0] = c[0];
        #pragma unroll
        for (int k = 1; k < CPL; ++k) s[k] = s[k - 1] + c[k];
        float tot = s[CPL - 1];
        #pragma unroll
        for (int o = 1; o < 32; o <<= 1) {
            float u = __shfl_up_sync(FULL, tot, o);
            if (lane >= o) tot += u;
        }
        excl = tot - s[CPL - 1];
    };

    float Dp[CPL];       // previous DP row for this warp's block
    float sC[CPL], eC;   // pipelined cost-scan of the current row

    #pragma unroll 1
    for (int t = -1; t < PP + NBLK - 1; ++t) {
        const int i = t - w;
        if (i == -1) {
            costscan(0, sC, eC);             // pipeline prep, one step early
        } else if (i >= 0 && i < PP) {
            // ---- pipelined: next row's cost + sum-scan (independent work) ----
            float sN[CPL], eN;
            if (i + 1 < PP) costscan(i + 1, sN, eN);

            // ---- boundary carries from the warp to the left (barrier-ordered) ----
            float bl, bm;  // D[i][j0-1], D[i-1][j0-1]
            if (w == 0) {
                bl = (i == 0) ? 0.0f : BIGV;   // D[0,0] seed; col -1 otherwise OOR
                bm = BIGV;                      // D[i-1][-1] is always out of range
            } else {
                bl = carry[w - 1][i];
                bm = (i > 0) ? carry[w - 1][i - 1] : BIGV;
            }

            // ---- t[k] = min(up-left, up) - S[j-1] ----
            float tt[CPL];
            float shin = __shfl_up_sync(FULL, Dp[CPL - 1], 1);
            if (i == 0) {
                #pragma unroll
                for (int k = 0; k < CPL; ++k) tt[k] = BIGV;
            } else {
                float mprev = (lane == 0) ? bm : shin;
                tt[0] = fminf(mprev, Dp[0]) - eC;
                #pragma unroll
                for (int k = 1; k < CPL; ++k)
                    tt[k] = fminf(Dp[k - 1], Dp[k]) - (eC + sC[k - 1]);
            }

            // ---- prefix-min with left-entry bl injected at position -1 ----
            float q[CPL];
            q[0] = (lane == 0) ? fminf(bl, tt[0]) : tt[0];
            #pragma unroll
            for (int k = 1; k < CPL; ++k) q[k] = fminf(q[k - 1], tt[k]);

            float mt = q[CPL - 1];
            #pragma unroll
            for (int o = 1; o < 32; o <<= 1)
                mt = fminf(mt, __shfl_up_sync(FULL, mt, o));  // OOR self-min: no-op
            float eprev = __shfl_up_sync(FULL, mt, 1);
            if (lane == 0) eprev = BIGV;

            float cur[CPL];
            #pragma unroll
            for (int k = 0; k < CPL; ++k)
                cur[k] = (eC + sC[k]) + fminf(eprev, q[k]);

            // ---- publish carry for the warp to the right ----
            if (w < NBLK - 1 && lane == 31) carry[w][i] = cur[CPL - 1];

            // ---- output: cols 992..1023 = lanes 28..31 of last warp ----
            if (w == NBLK - 1 && lane >= 28) {
                float* po = outb + i * LOUT + (lane - 28) * CPL;
                *reinterpret_cast<float4*>(po)     = make_float4(cur[0], cur[1], cur[2], cur[3]);
                *reinterpret_cast<float4*>(po + 4) = make_float4(cur[4], cur[5], cur[6], cur[7]);
            }

            #pragma unroll
            for (int k = 0; k < CPL; ++k) Dp[k] = cur[k];
            #pragma unroll
            for (int k = 0; k < CPL; ++k) sC[k] = sN[k];
            eC = eN;
        }
        __syncthreads();
    }
}

extern "C" void kernel_launch(void* const* d_in, const int* in_sizes, int n_in,
                              void* d_out, int out_size) {
    const float* x     = (const float*)d_in[0];   // [32, 12, 1024]
    const float* patts = (const float*)d_in[1];   // [32, 12, 32]
    float* out = (float*)d_out;                   // [32, 32, 32, 32]
    (void)in_sizes; (void)n_in; (void)out_size;
    dtw_fused_kernel<<<NB * NP, 128>>>(x, patts, out);
}

// round 7
// speedup vs baseline: 1.3049x; 1.2616x over previous
#include <cuda_runtime.h>
#include <cuda_bf16.h>

#define FULL 0xffffffffu

namespace {
constexpr int NB   = 32;
constexpr int NP   = 32;
constexpr int DD   = 12;
constexpr int PP   = 32;
constexpr int LL   = 1024;
constexpr int LOUT = 32;
constexpr int CPL  = 8;            // cols per lane
constexpr int WBLK = 32 * CPL;     // 256 cols per warp
constexpr int NBLK = LL / WBLK;    // 4 warps per (b,n)
constexpr float BIGV = 1e30f;
}

// One CTA (4 warps) per (b, n); warp w owns column block w. Diagonal wavefront
// (step t: warp w does row i = t - w) with one __syncthreads per step; carries
// cross warps via barrier-ordered smem.
//
// Row recurrence (w == 1 exactly, RHO = 1.0):
//   cur[j] = c[j] + min(m[j], cur[j-1]),  m[j] = min(D[i-1,j-1], D[i-1,j])
// is a composition of affine-min maps f_j(v) = min(beta_j, v + alpha_j) with
// alpha = c, beta = c + m, and composition
//   (f2 o f1) = (alpha1+alpha2, min(beta2, beta1+alpha2)).
// One composite Kogge-Stone scan (5 hops, 2 independent shfls per hop) replaces
// the former sum-scan + dependent min-scan (~10 dependent shfl hops).
__global__ void __launch_bounds__(128, 3)
dtw_fused_kernel(const float* __restrict__ x,
                 const float* __restrict__ patts,
                 float* __restrict__ out)
{
    const int gid  = blockIdx.x;        // 0..1023
    const int b    = gid >> 5;
    const int n    = gid & 31;
    const int w    = threadIdx.x >> 5;  // column block 0..3
    const int lane = threadIdx.x & 31;

    __shared__ float carry[NBLK - 1][PP];   // carry[w][i] = D[i][(w+1)*WBLK - 1]

    // lane holds patts[n][d][lane]; store -2*p for the FMA form of sqdist.
    float prow[DD];
    float p2 = 0.0f;
    {
        const float* pp = patts + n * (DD * PP) + lane;
        #pragma unroll
        for (int d = 0; d < DD; ++d) {
            float v = pp[d * PP];
            p2 = fmaf(v, v, p2);
            prow[d] = -2.0f * v;
        }
    }

    // x chunk for this warp's column block, reused by all 32 rows.
    const float* xb = x + b * (DD * LL);
    const int j0 = w * WBLK;
    float xr[DD][CPL];
    float x2[CPL] = {0.f, 0.f, 0.f, 0.f, 0.f, 0.f, 0.f, 0.f};
    #pragma unroll
    for (int d = 0; d < DD; ++d) {
        const float* px = xb + d * LL + j0 + CPL * lane;
        float4 v0 = *reinterpret_cast<const float4*>(px);
        float4 v1 = *reinterpret_cast<const float4*>(px + 4);
        xr[d][0] = v0.x; xr[d][1] = v0.y; xr[d][2] = v0.z; xr[d][3] = v0.w;
        xr[d][4] = v1.x; xr[d][5] = v1.y; xr[d][6] = v1.z; xr[d][7] = v1.w;
        #pragma unroll
        for (int k = 0; k < CPL; ++k) x2[k] = fmaf(xr[d][k], xr[d][k], x2[k]);
    }

    float* outb = out + ((b * NP + n) * PP) * LOUT;
    float Dp[CPL];   // previous DP row for this warp's block

    #pragma unroll 1
    for (int t = 0; t < PP + NBLK - 1; ++t) {
        const int i = t - w;
        if (i >= 0 && i < PP) {
            // ---- cost row c[k] (alpha) ----
            float p2b = __shfl_sync(FULL, p2, i);
            float c[CPL];
            #pragma unroll
            for (int k = 0; k < CPL; ++k) c[k] = p2b + x2[k];
            #pragma unroll
            for (int d = 0; d < DD; ++d) {
                float pb = __shfl_sync(FULL, prow[d], i);
                #pragma unroll
                for (int k = 0; k < CPL; ++k) c[k] = fmaf(pb, xr[d][k], c[k]);
            }

            // ---- boundary carries (barrier-ordered smem) ----
            float bl, bm;  // D[i][j0-1], D[i-1][j0-1]
            if (w == 0) {
                bl = (i == 0) ? 0.0f : BIGV;   // D[0,0] seed enters as v
                bm = BIGV;
            } else {
                bl = carry[w - 1][i];
                bm = (i > 0) ? carry[w - 1][i - 1] : BIGV;
            }

            // ---- local inclusive composites (A = prefix sum of c, B = bound) ----
            float A[CPL], Bv[CPL];
            float shin = __shfl_up_sync(FULL, Dp[CPL - 1], 1);
            if (i == 0) {
                A[0] = c[0]; Bv[0] = BIGV;
                #pragma unroll
                for (int k = 1; k < CPL; ++k) { A[k] = A[k - 1] + c[k]; Bv[k] = BIGV; }
            } else {
                float m0 = fminf((lane == 0) ? bm : shin, Dp[0]);
                A[0]  = c[0];
                Bv[0] = c[0] + m0;
                #pragma unroll
                for (int k = 1; k < CPL; ++k) {
                    float mk = fminf(Dp[k - 1], Dp[k]);
                    A[k]  = A[k - 1] + c[k];
                    Bv[k] = fminf(c[k] + mk, Bv[k - 1] + c[k]);
                }
            }

            // ---- single composite warp scan over lane maps ----
            float Aw = A[CPL - 1], Bw = Bv[CPL - 1];
            #pragma unroll
            for (int o = 1; o < 32; o <<= 1) {
                float Au = __shfl_up_sync(FULL, Aw, o);
                float Bu = __shfl_up_sync(FULL, Bw, o);
                if (lane >= o) {
                    Bw = fminf(Bw, Bu + Aw);  // uses pre-update Aw
                    Aw = Aw + Au;
                }
            }
            float Ae = __shfl_up_sync(FULL, Aw, 1);
            float Be = __shfl_up_sync(FULL, Bw, 1);
            float vin = (lane == 0) ? bl : fminf(Be, bl + Ae);

            // ---- outputs: cur[k] = min(B[k], vin + A[k]) ----
            float cur[CPL];
            #pragma unroll
            for (int k = 0; k < CPL; ++k)
                cur[k] = fminf(Bv[k], vin + A[k]);

            // ---- publish carry for the warp to the right ----
            if (w < NBLK - 1 && lane == 31) carry[w][i] = cur[CPL - 1];

            // ---- output: cols 992..1023 = lanes 28..31 of last warp ----
            if (w == NBLK - 1 && lane >= 28) {
                float* po = outb + i * LOUT + (lane - 28) * CPL;
                *reinterpret_cast<float4*>(po)     = make_float4(cur[0], cur[1], cur[2], cur[3]);
                *reinterpret_cast<float4*>(po + 4) = make_float4(cur[4], cur[5], cur[6], cur[7]);
            }

            #pragma unroll
            for (int k = 0; k < CPL; ++k) Dp[k] = cur[k];
        }
        __syncthreads();
    }
}

extern "C" void kernel_launch(void* const* d_in, const int* in_sizes, int n_in,
                              void* d_out, int out_size) {
    const float* x     = (const float*)d_in[0];   // [32, 12, 1024]
    const float* patts = (const float*)d_in[1];   // [32, 12, 32]
    float* out = (float*)d_out;                   // [32, 32, 32, 32]
    (void)in_sizes; (void)n_in; (void)out_size;
    dtw_fused_kernel<<<NB * NP, 128>>>(x, patts, out);
}

// round 8
// speedup vs baseline: 1.3614x; 1.0433x over previous
#include <cuda_runtime.h>
#include <cuda_bf16.h>

#define FULL 0xffffffffu

namespace {
constexpr int NB   = 32;
constexpr int NP   = 32;
constexpr int DD   = 12;
constexpr int PP   = 32;
constexpr int LL   = 1024;
constexpr int LOUT = 32;
constexpr int CPL  = 8;            // cols per lane
constexpr int CP2  = CPL / 2;      // packed f32x2 pairs per lane
constexpr int WBLK = 32 * CPL;     // 256 cols per warp
constexpr int NBLK = LL / WBLK;    // 4 warps per (b,n)
constexpr float BIGV = 1e30f;
}

typedef unsigned long long u64;

// Blackwell packed fp32x2 ops (FFMA2/FADD2 in SASS — only reachable via PTX).
__device__ __forceinline__ u64 pack2(float lo, float hi) {
    u64 r; asm("mov.b64 %0, {%1, %2};" : "=l"(r) : "f"(lo), "f"(hi)); return r;
}
__device__ __forceinline__ void unpack2(u64 v, float& lo, float& hi) {
    asm("mov.b64 {%0, %1}, %2;" : "=f"(lo), "=f"(hi) : "l"(v));
}
__device__ __forceinline__ u64 ffma2(u64 a, u64 b, u64 c) {
    u64 d; asm("fma.rn.f32x2 %0, %1, %2, %3;" : "=l"(d) : "l"(a), "l"(b), "l"(c)); return d;
}
__device__ __forceinline__ u64 fadd2(u64 a, u64 b) {
    u64 d; asm("add.rn.f32x2 %0, %1, %2;" : "=l"(d) : "l"(a), "l"(b)); return d;
}

// One CTA (4 warps) per (b, n); warp w owns column block w. Diagonal wavefront
// (step t: warp w does row i = t - w), one __syncthreads per step; carries
// cross warps via barrier-ordered smem.
//
// Row recurrence (w == 1 exactly, RHO = 1.0):
//   cur[j] = c[j] + min(m[j], cur[j-1]),  m[j] = min(D[i-1,j-1], D[i-1,j])
// as composition of affine-min maps f_j(v) = min(beta_j, v + alpha_j),
// (f2 o f1) = (alpha1+alpha2, min(beta2, beta1+alpha2)): one composite
// Kogge-Stone scan (5 hops). Cost row computed with packed f32x2 FMAs.
__global__ void __launch_bounds__(128, 3)
dtw_fused_kernel(const float* __restrict__ x,
                 const float* __restrict__ patts,
                 float* __restrict__ out)
{
    const int gid  = blockIdx.x;        // 0..1023
    const int b    = gid >> 5;
    const int n    = gid & 31;
    const int w    = threadIdx.x >> 5;  // column block 0..3
    const int lane = threadIdx.x & 31;

    __shared__ float carry[NBLK - 1][PP];   // carry[w][i] = D[i][(w+1)*WBLK - 1]

    // lane holds patts[n][d][lane]; store -2*p for the FMA form of sqdist.
    float prow[DD];
    float p2 = 0.0f;
    {
        const float* pp = patts + n * (DD * PP) + lane;
        #pragma unroll
        for (int d = 0; d < DD; ++d) {
            float v = pp[d * PP];
            p2 = fmaf(v, v, p2);
            prow[d] = -2.0f * v;
        }
    }

    // x chunk for this warp's column block (packed f32x2), reused by all rows.
    const float* xb = x + b * (DD * LL);
    const int j0 = w * WBLK;
    u64 xp[DD][CP2];
    u64 px2[CP2];
    {
        u64 z = pack2(0.0f, 0.0f);
        #pragma unroll
        for (int k2 = 0; k2 < CP2; ++k2) px2[k2] = z;
    }
    #pragma unroll
    for (int d = 0; d < DD; ++d) {
        const float* px = xb + d * LL + j0 + CPL * lane;
        float4 v0 = *reinterpret_cast<const float4*>(px);
        float4 v1 = *reinterpret_cast<const float4*>(px + 4);
        xp[d][0] = pack2(v0.x, v0.y);
        xp[d][1] = pack2(v0.z, v0.w);
        xp[d][2] = pack2(v1.x, v1.y);
        xp[d][3] = pack2(v1.z, v1.w);
        #pragma unroll
        for (int k2 = 0; k2 < CP2; ++k2)
            px2[k2] = ffma2(xp[d][k2], xp[d][k2], px2[k2]);
    }

    float* outb = out + ((b * NP + n) * PP) * LOUT;
    float Dp[CPL];   // previous DP row for this warp's block

    #pragma unroll 1
    for (int t = 0; t < PP + NBLK - 1; ++t) {
        const int i = t - w;
        if (i >= 0 && i < PP) {
            // ---- cost row c[k] (alpha), packed f32x2 ----
            float p2b = __shfl_sync(FULL, p2, i);
            u64 p2b2 = pack2(p2b, p2b);
            u64 cc[CP2];
            #pragma unroll
            for (int k2 = 0; k2 < CP2; ++k2) cc[k2] = fadd2(p2b2, px2[k2]);
            #pragma unroll
            for (int d = 0; d < DD; ++d) {
                float pb = __shfl_sync(FULL, prow[d], i);
                u64 pbb = pack2(pb, pb);
                #pragma unroll
                for (int k2 = 0; k2 < CP2; ++k2)
                    cc[k2] = ffma2(pbb, xp[d][k2], cc[k2]);
            }
            float c[CPL];
            #pragma unroll
            for (int k2 = 0; k2 < CP2; ++k2)
                unpack2(cc[k2], c[2 * k2], c[2 * k2 + 1]);

            // ---- boundary carries (barrier-ordered smem) ----
            float bl, bm;  // D[i][j0-1], D[i-1][j0-1]
            if (w == 0) {
                bl = (i == 0) ? 0.0f : BIGV;   // D[0,0] seed enters as v
                bm = BIGV;
            } else {
                bl = carry[w - 1][i];
                bm = (i > 0) ? carry[w - 1][i - 1] : BIGV;
            }

            // ---- local inclusive composites (A = prefix sum of c, B = bound) ----
            float A[CPL], Bv[CPL];
            float shin = __shfl_up_sync(FULL, Dp[CPL - 1], 1);
            if (i == 0) {
                A[0] = c[0]; Bv[0] = BIGV;
                #pragma unroll
                for (int k = 1; k < CPL; ++k) { A[k] = A[k - 1] + c[k]; Bv[k] = BIGV; }
            } else {
                float m0 = fminf((lane == 0) ? bm : shin, Dp[0]);
                A[0]  = c[0];
                Bv[0] = c[0] + m0;
                #pragma unroll
                for (int k = 1; k < CPL; ++k) {
                    float mk = fminf(Dp[k - 1], Dp[k]);
                    A[k]  = A[k - 1] + c[k];
                    Bv[k] = fminf(c[k] + mk, Bv[k - 1] + c[k]);
                }
            }

            // ---- single composite warp scan over lane maps ----
            float Aw = A[CPL - 1], Bw = Bv[CPL - 1];
            #pragma unroll
            for (int o = 1; o < 32; o <<= 1) {
                float Au = __shfl_up_sync(FULL, Aw, o);
                float Bu = __shfl_up_sync(FULL, Bw, o);
                if (lane >= o) {
                    Bw = fminf(Bw, Bu + Aw);  // uses pre-update Aw
                    Aw = Aw + Au;
                }
            }
            float Ae = __shfl_up_sync(FULL, Aw, 1);
            float Be = __shfl_up_sync(FULL, Bw, 1);
            float vin = (lane == 0) ? bl : fminf(Be, bl + Ae);

            // ---- outputs: cur[k] = min(B[k], vin + A[k]) ----
            float cur[CPL];
            #pragma unroll
            for (int k = 0; k < CPL; ++k)
                cur[k] = fminf(Bv[k], vin + A[k]);

            // ---- publish carry for the warp to the right ----
            if (w < NBLK - 1 && lane == 31) carry[w][i] = cur[CPL - 1];

            // ---- output: cols 992..1023 = lanes 28..31 of last warp ----
            if (w == NBLK - 1 && lane >= 28) {
                float* po = outb + i * LOUT + (lane - 28) * CPL;
                *reinterpret_cast<float4*>(po)     = make_float4(cur[0], cur[1], cur[2], cur[3]);
                *reinterpret_cast<float4*>(po + 4) = make_float4(cur[4], cur[5], cur[6], cur[7]);
            }

            #pragma unroll
            for (int k = 0; k < CPL; ++k) Dp[k] = cur[k];
        }
        __syncthreads();
    }
}

extern "C" void kernel_launch(void* const* d_in, const int* in_sizes, int n_in,
                              void* d_out, int out_size) {
    const float* x     = (const float*)d_in[0];   // [32, 12, 1024]
    const float* patts = (const float*)d_in[1];   // [32, 12, 32]
    float* out = (float*)d_out;                   // [32, 32, 32, 32]
    (void)in_sizes; (void)n_in; (void)out_size;
    dtw_fused_kernel<<<NB * NP, 128>>>(x, patts, out);
}